// round 3
// baseline (speedup 1.0000x reference)
#include <cuda_runtime.h>

#define TT 128
#define BB 512
#define QQ 50
#define BQ (BB * QQ)
#define NUNITS ((TT - 1) * BB)     // 65024 (t,b) units with a loss row
#define GAMMA_F 0.99f
#define RST 52                      // padded smem row stride (floats), 16B aligned
#define UNITS 5                     // (t,b) units per pair-kernel block

// Scratch: discounted returns, laid out so unit gu=(t*BB+b) occupies
// g_ret[gu*QQ .. gu*QQ+49] (same as input layout since t*BQ + b*QQ == gu*QQ).
__device__ float g_ret[(TT - 1) * BQ];

// ---------------------------------------------------------------------------
// Kernel 1: backward recurrence, one thread per (b,q) chain.
// Chunked by 8 so the compiler batches independent loads (MLP) between the
// serial carry updates. Also zeroes the poisoned last output row.
// ---------------------------------------------------------------------------
__global__ __launch_bounds__(128)
void k_returns(const float* __restrict__ reward,
               const int*   __restrict__ step_type,
               const float* __restrict__ discount,
               const float* __restrict__ tvalue,
               float*       __restrict__ out)
{
    const int n = blockIdx.x * 128 + threadIdx.x;   // 0 .. 25599
    if (n < BB) out[(TT - 1) * BB + n] = 0.0f;      // loss[T-1] = 0
    if (n >= BQ) return;
    const int b = n / QQ;

    float carry = tvalue[(TT - 1) * BQ + n];

    // Main chunks: t = t0, t0-1, ..., t0-7 for t0 = 126, 118, ..., 14
    for (int t0 = TT - 2; t0 >= 7; t0 -= 8) {
        float tv[8], r[8], d[8];
        int   il[8];
        #pragma unroll
        for (int k = 0; k < 8; ++k) {
            const int t = t0 - k;
            tv[k] = tvalue[t * BQ + n];
            r[k]  = reward[(t + 1) * BB + b];
            d[k]  = discount[(t + 1) * BB + b];
            il[k] = step_type[t * BB + b];
        }
        #pragma unroll
        for (int k = 0; k < 8; ++k) {
            const int t = t0 - k;
            float acc = fmaf(carry, d[k] * GAMMA_F, r[k]);
            carry = (il[k] == 2) ? tv[k] : acc;
            g_ret[t * BQ + n] = carry;
        }
    }
    // Tail: t = 6 .. 0
    #pragma unroll
    for (int t = 6; t >= 0; --t) {
        float tv = tvalue[t * BQ + n];
        float r  = reward[(t + 1) * BB + b];
        float d  = discount[(t + 1) * BB + b] * GAMMA_F;
        bool  isl = (step_type[t * BB + b] == 2);
        float acc = fmaf(carry, d, r);
        carry = isl ? tv : acc;
        g_ret[t * BQ + n] = carry;
    }
}

// ---------------------------------------------------------------------------
// Kernel 2: pairwise quantile-Huber.
//   x = ret_i - v_j
//   m = min(|x|,1)                      (1 FMNMX, abs folded)
//   c = copysign(m,x) = (x&sign)|m      (1 LOP3)
//   t = x - 0.5c                        (packed fma)
//   h = c*t   (>=0),   sign(x)*h = m*t
//   S += h (packed fma),  D += sign*h (packed fma)
//   loss_j = 0.5*S + (tau_j - 0.5)*D
// ---------------------------------------------------------------------------

#define PAIR2(r2_) do {                                                        \
    unsigned long long x2_, c2_, m2_, t2_;                                     \
    asm("add.rn.f32x2 %0, %1, %2;" : "=l"(x2_) : "l"(r2_), "l"(nv2));          \
    float xl_, xh_;                                                            \
    asm("mov.b64 {%0, %1}, %2;" : "=f"(xl_), "=f"(xh_) : "l"(x2_));            \
    float ml_ = fminf(fabsf(xl_), 1.0f);                                       \
    float mh_ = fminf(fabsf(xh_), 1.0f);                                       \
    float cl_ = __int_as_float((__float_as_int(xl_) & 0x80000000) |            \
                               __float_as_int(ml_));                           \
    float ch_ = __int_as_float((__float_as_int(xh_) & 0x80000000) |            \
                               __float_as_int(mh_));                           \
    asm("mov.b64 %0, {%1, %2};" : "=l"(c2_) : "f"(cl_), "f"(ch_));             \
    asm("mov.b64 %0, {%1, %2};" : "=l"(m2_) : "f"(ml_), "f"(mh_));             \
    asm("fma.rn.f32x2 %0, %1, %2, %3;" : "=l"(t2_)                             \
        : "l"(c2_), "l"(MH2), "l"(x2_));                                       \
    asm("fma.rn.f32x2 %0, %1, %2, %0;" : "+l"(S2) : "l"(c2_), "l"(t2_));       \
    asm("fma.rn.f32x2 %0, %1, %2, %0;" : "+l"(D2) : "l"(m2_), "l"(t2_));       \
} while (0)

__global__ __launch_bounds__(256)
void k_pairs(const float* __restrict__ value,
             float*       __restrict__ out)
{
    __shared__ __align__(16) float s_ret[UNITS][RST];
    __shared__ float s_part[UNITS][QQ];

    const int tid = threadIdx.x;
    const int gu0 = blockIdx.x * UNITS;

    // Stage 5 return rows (contiguous 1000B in gmem -> coalesced).
    if (tid < UNITS * QQ) {
        const int u  = tid / QQ;
        const int q  = tid - u * QQ;
        const int gu = gu0 + u;
        if (gu < NUNITS) s_ret[u][q] = g_ret[gu * QQ + q];
    }
    __syncthreads();

    if (tid < UNITS * QQ) {
        const int u  = tid / QQ;
        const int j  = tid - u * QQ;
        const int gu = gu0 + u;
        if (gu < NUNITS) {
            const float vj = value[gu * QQ + j];
            unsigned long long nv2;
            {
                float nv = -vj;
                asm("mov.b64 %0, {%1, %1};" : "=l"(nv2) : "f"(nv));
            }
            const unsigned long long MH2 = 0xBF000000BF000000ULL; // (-0.5,-0.5)
            unsigned long long S2 = 0ULL, D2 = 0ULL;

            const ulonglong2* rp2 =
                reinterpret_cast<const ulonglong2*>(&s_ret[u][0]);
            #pragma unroll
            for (int p = 0; p < 12; ++p) {          // 48 returns via LDS.128
                ulonglong2 rr = rp2[p];
                PAIR2(rr.x);
                PAIR2(rr.y);
            }
            {                                        // returns 48, 49
                unsigned long long rt_ =
                    *reinterpret_cast<const unsigned long long*>(&s_ret[u][48]);
                PAIR2(rt_);
            }

            float sl, sh, dl, dh;
            asm("mov.b64 {%0, %1}, %2;" : "=f"(sl), "=f"(sh) : "l"(S2));
            asm("mov.b64 {%0, %1}, %2;" : "=f"(dl), "=f"(dh) : "l"(D2));
            const float S = sl + sh;
            const float D = dl + dh;
            const float tau = ((float)j + 0.5f) * (1.0f / QQ);
            s_part[u][j] = fmaf(tau - 0.5f, D, 0.5f * S);
        }
    }
    __syncthreads();

    // Deterministic fixed-order j-reduction, one thread per unit.
    if (tid < UNITS) {
        const int gu = gu0 + tid;
        if (gu < NUNITS) {
            float s = 0.0f;
            #pragma unroll
            for (int j = 0; j < QQ; ++j) s += s_part[tid][j];
            out[gu] = s * (1.0f / QQ);   // out index t*BB+b == gu
        }
    }
}

extern "C" void kernel_launch(void* const* d_in, const int* in_sizes, int n_in,
                              void* d_out, int out_size)
{
    const float* reward    = (const float*)d_in[0];
    const int*   step_type = (const int*)  d_in[1];
    const float* discount  = (const float*)d_in[2];
    const float* value     = (const float*)d_in[3];
    const float* tvalue    = (const float*)d_in[4];
    float*       out       = (float*)d_out;

    k_returns<<<200, 128>>>(reward, step_type, discount, tvalue, out);

    const int nblocks = (NUNITS + UNITS - 1) / UNITS;   // 13005
    k_pairs<<<nblocks, 256>>>(value, out);
}

// round 4
// speedup vs baseline: 1.3020x; 1.3020x over previous
#include <cuda_runtime.h>

#define TT 128
#define BB 512
#define QQ 50
#define BQ (BB * QQ)                 // 25600
#define NUNITS ((TT - 1) * BB)       // 65024
#define GAMMA_F 0.99f
#define NCH 8
#define CHL 16
#define RST 52                       // padded smem row stride, 16B aligned
#define UNITS 5
#define JP 25                        // j-pairs per unit

__device__ float g_ret[(TT - 1) * BQ];
__device__ float g_A[NCH * BQ];
__device__ float g_B[NCH * BQ];

// ---------------------------------------------------------------------------
// Kernel 1: per-chunk affine composite (A,B) of the backward recurrence.
// Thread = (n, c) with n=(b,q) chain id, c=chunk. 204,800 threads.
// carry_t = a_t*carry_{t+1} + b_t ;  a_t = il? 0 : g*d[t+1],  b_t = il? tv : r[t+1]
// ---------------------------------------------------------------------------
__global__ __launch_bounds__(128)
void k_scan(const float* __restrict__ reward,
            const int*   __restrict__ step_type,
            const float* __restrict__ discount,
            const float* __restrict__ tvalue,
            float*       __restrict__ out)
{
    const int n = blockIdx.x * 128 + threadIdx.x;   // 0..25599
    const int c = blockIdx.y;
    if (c == 0 && n < BB) out[(TT - 1) * BB + n] = 0.0f;   // poisoned last row
    const int b = n / QQ;
    const int lo = c * CHL;
    const int hi = (c == NCH - 1) ? (TT - 2) : (lo + CHL - 1);

    float A = 1.0f, Bv = 0.0f;
    #pragma unroll
    for (int k = 0; k < CHL; ++k) {
        const int t = hi - k;
        if (t >= lo) {
            float tv = tvalue[t * BQ + n];
            int   il = step_type[t * BB + b];
            float r  = reward[(t + 1) * BB + b];
            float d  = discount[(t + 1) * BB + b] * GAMMA_F;
            float a  = (il == 2) ? 0.0f : d;
            float bb = (il == 2) ? tv   : r;
            A  = a * A;
            Bv = fmaf(a, Bv, bb);
        }
    }
    g_A[c * BQ + n] = A;
    g_B[c * BQ + n] = Bv;
}

// ---------------------------------------------------------------------------
// Kernel 2: compose tail chunks to get this chunk's seed, then walk the
// chunk writing returns. Thread = (n, c). 204,800 threads.
// ---------------------------------------------------------------------------
__global__ __launch_bounds__(128)
void k_fill(const float* __restrict__ reward,
            const int*   __restrict__ step_type,
            const float* __restrict__ discount,
            const float* __restrict__ tvalue)
{
    const int n = blockIdx.x * 128 + threadIdx.x;
    const int c = blockIdx.y;
    const int b = n / QQ;

    float carry = tvalue[(TT - 1) * BQ + n];        // rets[127]
    #pragma unroll
    for (int cc = NCH - 1; cc > 0; --cc) {
        if (cc > c)
            carry = fmaf(g_A[cc * BQ + n], carry, g_B[cc * BQ + n]);
    }
    // carry == rets[hi+1] for this chunk

    const int lo = c * CHL;
    const int hi = (c == NCH - 1) ? (TT - 2) : (lo + CHL - 1);
    #pragma unroll
    for (int k = 0; k < CHL; ++k) {
        const int t = hi - k;
        if (t >= lo) {
            float tv = tvalue[t * BQ + n];
            int   il = step_type[t * BB + b];
            float r  = reward[(t + 1) * BB + b];
            float d  = discount[(t + 1) * BB + b] * GAMMA_F;
            float a  = (il == 2) ? 0.0f : d;
            float bb = (il == 2) ? tv   : r;
            carry = fmaf(a, carry, bb);             // il: exactly tv
            g_ret[t * BQ + n] = carry;
        }
    }
}

// ---------------------------------------------------------------------------
// Kernel 3: pairwise quantile-Huber, 2 i's (packed f32x2) x 2 j's per step.
//   x = ret_i - v_j;  m = min(|x|,1);  c = (x&sign)|m;  t = x - 0.5c
//   h = c*t (unsigned), sgn(x)*h = m*t
//   loss_j = 0.5*S_j + (tau_j - 0.5)*D_j,  S=sum h, D=sum sgn*h
// ---------------------------------------------------------------------------

#define PAIR2(r2_, nv2_, S2_, D2_) do {                                        \
    unsigned long long x2_, c2_, m2_, t2_;                                     \
    asm("add.rn.f32x2 %0, %1, %2;" : "=l"(x2_) : "l"(r2_), "l"(nv2_));         \
    float xl_, xh_;                                                            \
    asm("mov.b64 {%0, %1}, %2;" : "=f"(xl_), "=f"(xh_) : "l"(x2_));            \
    float ml_ = fminf(fabsf(xl_), 1.0f);                                       \
    float mh_ = fminf(fabsf(xh_), 1.0f);                                       \
    float cl_ = __int_as_float((__float_as_int(xl_) & 0x80000000) |            \
                               __float_as_int(ml_));                           \
    float ch_ = __int_as_float((__float_as_int(xh_) & 0x80000000) |            \
                               __float_as_int(mh_));                           \
    asm("mov.b64 %0, {%1, %2};" : "=l"(c2_) : "f"(cl_), "f"(ch_));             \
    asm("mov.b64 %0, {%1, %2};" : "=l"(m2_) : "f"(ml_), "f"(mh_));             \
    asm("fma.rn.f32x2 %0, %1, %2, %3;" : "=l"(t2_)                             \
        : "l"(c2_), "l"(MH2), "l"(x2_));                                       \
    asm("fma.rn.f32x2 %0, %1, %2, %0;" : "+l"(S2_) : "l"(c2_), "l"(t2_));      \
    asm("fma.rn.f32x2 %0, %1, %2, %0;" : "+l"(D2_) : "l"(m2_), "l"(t2_));      \
} while (0)

__global__ __launch_bounds__(128)
void k_pairs(const float* __restrict__ value,
             float*       __restrict__ out)
{
    __shared__ __align__(16) float s_ret[UNITS][RST];
    __shared__ float s_part[UNITS][QQ];

    const int tid = threadIdx.x;
    const int gu0 = blockIdx.x * UNITS;
    const int nu  = min(UNITS, NUNITS - gu0);       // valid units this block

    // Stage nu contiguous return rows (g_ret rows gu0..gu0+nu-1 are contiguous).
    const int nstage = nu * QQ;
    for (int idx = tid; idx < nstage; idx += 128) {
        const int u = idx / QQ;
        const int q = idx - u * QQ;
        s_ret[u][q] = g_ret[gu0 * QQ + idx];
    }
    __syncthreads();

    if (tid < UNITS * JP) {
        const int u  = tid / JP;
        const int jp = tid - u * JP;
        const int gu = gu0 + u;
        if (u < nu) {
            const float2 v2 = *(const float2*)&value[gu * QQ + 2 * jp];
            unsigned long long nv2a, nv2b;
            {
                float na = -v2.x, nb = -v2.y;
                asm("mov.b64 %0, {%1, %1};" : "=l"(nv2a) : "f"(na));
                asm("mov.b64 %0, {%1, %1};" : "=l"(nv2b) : "f"(nb));
            }
            const unsigned long long MH2 = 0xBF000000BF000000ULL; // (-0.5,-0.5)
            unsigned long long S2a = 0, D2a = 0, S2b = 0, D2b = 0;

            const ulonglong2* rp2 = (const ulonglong2*)&s_ret[u][0];
            #pragma unroll
            for (int p = 0; p < 12; ++p) {          // 48 returns via LDS.128
                ulonglong2 rr = rp2[p];
                PAIR2(rr.x, nv2a, S2a, D2a);
                PAIR2(rr.x, nv2b, S2b, D2b);
                PAIR2(rr.y, nv2a, S2a, D2a);
                PAIR2(rr.y, nv2b, S2b, D2b);
            }
            {                                        // returns 48, 49
                unsigned long long rt_ =
                    *(const unsigned long long*)&s_ret[u][48];
                PAIR2(rt_, nv2a, S2a, D2a);
                PAIR2(rt_, nv2b, S2b, D2b);
            }

            float sl, sh, dl, dh;
            asm("mov.b64 {%0, %1}, %2;" : "=f"(sl), "=f"(sh) : "l"(S2a));
            asm("mov.b64 {%0, %1}, %2;" : "=f"(dl), "=f"(dh) : "l"(D2a));
            float taua = (2 * jp + 0.5f) * (1.0f / QQ);
            s_part[u][2 * jp] =
                fmaf(taua - 0.5f, dl + dh, 0.5f * (sl + sh));

            asm("mov.b64 {%0, %1}, %2;" : "=f"(sl), "=f"(sh) : "l"(S2b));
            asm("mov.b64 {%0, %1}, %2;" : "=f"(dl), "=f"(dh) : "l"(D2b));
            float taub = (2 * jp + 1.5f) * (1.0f / QQ);
            s_part[u][2 * jp + 1] =
                fmaf(taub - 0.5f, dl + dh, 0.5f * (sl + sh));
        }
    }
    __syncthreads();

    // Deterministic fixed-order j-reduction, one thread per unit.
    if (tid < nu) {
        float s = 0.0f;
        #pragma unroll
        for (int j = 0; j < QQ; ++j) s += s_part[tid][j];
        out[gu0 + tid] = s * (1.0f / QQ);           // out idx t*BB+b == gu
    }
}

extern "C" void kernel_launch(void* const* d_in, const int* in_sizes, int n_in,
                              void* d_out, int out_size)
{
    const float* reward    = (const float*)d_in[0];
    const int*   step_type = (const int*)  d_in[1];
    const float* discount  = (const float*)d_in[2];
    const float* value     = (const float*)d_in[3];
    const float* tvalue    = (const float*)d_in[4];
    float*       out       = (float*)d_out;

    dim3 gs(BQ / 128, NCH);                          // (200, 8)
    k_scan<<<gs, 128>>>(reward, step_type, discount, tvalue, out);
    k_fill<<<gs, 128>>>(reward, step_type, discount, tvalue);

    const int nblocks = (NUNITS + UNITS - 1) / UNITS;   // 13005
    k_pairs<<<nblocks, 128>>>(value, out);
}

// round 5
// speedup vs baseline: 1.3510x; 1.0377x over previous
#include <cuda_runtime.h>

#define TT 128
#define BB 512
#define QQ 50
#define BQ (BB * QQ)                 // 25600
#define GAMMA_F 0.99f
#define NCH 8
#define CHL 16
#define TILE 32                      // t-rows per pairs block (2 chunks)
#define RST 52                       // smem row stride, 16B aligned
#define NTHR 160                     // 5 warps; 32*25 items = 5 exact passes

// Per-chunk affine composites (A,B) per chain: rets[chunk_lo] = A*rets[chunk_hi+1] + B
__device__ float2 g_AB[NCH * BQ];

// ---------------------------------------------------------------------------
// Kernel 1: chunk composites. Thread = 2 q-adjacent chains (same b since QQ
// even) in one chunk. 102,400 threads.
// ---------------------------------------------------------------------------
__global__ __launch_bounds__(128)
void k_scan(const float* __restrict__ reward,
            const int*   __restrict__ step_type,
            const float* __restrict__ discount,
            const float* __restrict__ tvalue,
            float*       __restrict__ out)
{
    const int p = blockIdx.x * 128 + threadIdx.x;   // 0..12799 chain-pair
    const int c = blockIdx.y;
    if (c == 0 && p < BB) out[(TT - 1) * BB + p] = 0.0f;   // poisoned last row
    const int n = 2 * p;
    const int b = n / QQ;                            // same b for both chains
    const int lo = c * CHL;
    const int hi = (c == NCH - 1) ? (TT - 2) : (lo + CHL - 1);

    float A = 1.0f, B0 = 0.0f, B1 = 0.0f;
    #pragma unroll
    for (int k = 0; k < CHL; ++k) {
        const int t = hi - k;
        if (t >= lo) {
            float2 tv = *(const float2*)&tvalue[t * BQ + n];
            int   il = step_type[t * BB + b];
            float r  = reward[(t + 1) * BB + b];
            float d  = discount[(t + 1) * BB + b] * GAMMA_F;
            float a  = (il == 2) ? 0.0f : d;
            float bl = (il == 2) ? tv.x : r;
            float bh = (il == 2) ? tv.y : r;
            A  = a * A;
            B0 = fmaf(a, B0, bl);
            B1 = fmaf(a, B1, bh);
        }
    }
    g_AB[c * BQ + n]     = make_float2(A, B0);
    g_AB[c * BQ + n + 1] = make_float2(A, B1);
}

// ---------------------------------------------------------------------------
// Kernel 2 (fused): per (b, 32-t tile): compose seed from chunk composites,
// walk the recurrence in smem, then pairwise quantile-Huber.
// ---------------------------------------------------------------------------

#define PAIR2(r2_, nv2_, S2_, D2_) do {                                        \
    unsigned long long x2_, c2_, m2_, t2_;                                     \
    asm("add.rn.f32x2 %0, %1, %2;" : "=l"(x2_) : "l"(r2_), "l"(nv2_));         \
    float xl_, xh_;                                                            \
    asm("mov.b64 {%0, %1}, %2;" : "=f"(xl_), "=f"(xh_) : "l"(x2_));            \
    float ml_ = fminf(fabsf(xl_), 1.0f);                                       \
    float mh_ = fminf(fabsf(xh_), 1.0f);                                       \
    float cl_ = __int_as_float((__float_as_int(xl_) & 0x80000000) |            \
                               __float_as_int(ml_));                           \
    float ch_ = __int_as_float((__float_as_int(xh_) & 0x80000000) |            \
                               __float_as_int(mh_));                           \
    asm("mov.b64 %0, {%1, %2};" : "=l"(c2_) : "f"(cl_), "f"(ch_));             \
    asm("mov.b64 %0, {%1, %2};" : "=l"(m2_) : "f"(ml_), "f"(mh_));             \
    asm("fma.rn.f32x2 %0, %1, %2, %3;" : "=l"(t2_)                             \
        : "l"(c2_), "l"(MH2), "l"(x2_));                                       \
    asm("fma.rn.f32x2 %0, %1, %2, %0;" : "+l"(S2_) : "l"(c2_), "l"(t2_));      \
    asm("fma.rn.f32x2 %0, %1, %2, %0;" : "+l"(D2_) : "l"(m2_), "l"(t2_));      \
} while (0)

__global__ __launch_bounds__(NTHR)
void k_fused(const float* __restrict__ reward,
             const int*   __restrict__ step_type,
             const float* __restrict__ discount,
             const float* __restrict__ value,
             const float* __restrict__ tvalue,
             float*       __restrict__ out)
{
    __shared__ __align__(16) float s_ret[TILE][RST];
    __shared__ float s_part[TILE][QQ];
    __shared__ float s_r[TILE], s_d[TILE];
    __shared__ int   s_il[TILE];

    const int tid = threadIdx.x;
    const int b   = blockIdx.x;
    const int c0  = blockIdx.y;                      // tile 0..3
    const int lo  = c0 * TILE;
    const int hi  = (c0 == 3) ? (TT - 2) : (lo + TILE - 1);
    const int nu  = hi - lo + 1;                     // 32 or 31

    // ---- Stage tvalue rows lo..hi (float2) + per-t scalars ----
    const int nstage = nu * (QQ / 2);
    for (int idx = tid; idx < nstage; idx += NTHR) {
        const int u  = idx / (QQ / 2);
        const int q2 = idx - u * (QQ / 2);
        ((float2*)&s_ret[u][0])[q2] =
            *(const float2*)&tvalue[(lo + u) * BQ + b * QQ + 2 * q2];
    }
    if (tid < nu) {
        const int t = lo + tid;
        s_il[tid] = step_type[t * BB + b];
        s_r[tid]  = reward[(t + 1) * BB + b];
        s_d[tid]  = discount[(t + 1) * BB + b] * GAMMA_F;
    }
    __syncthreads();

    // ---- Seed compose (chunks above this tile) + in-smem walk ----
    if (tid < QQ) {
        float carry = tvalue[(TT - 1) * BQ + b * QQ + tid];   // rets[127]
        for (int cc = NCH - 1; cc >= 2 * c0 + 2; --cc) {
            float2 ab = g_AB[cc * BQ + b * QQ + tid];
            carry = fmaf(ab.x, carry, ab.y);
        }
        // carry == rets[hi+1]
        for (int k = nu - 1; k >= 0; --k) {
            float tv = s_ret[k][tid];
            float a  = (s_il[k] == 2) ? 0.0f : s_d[k];
            float bb = (s_il[k] == 2) ? tv   : s_r[k];
            carry = fmaf(a, carry, bb);
            s_ret[k][tid] = carry;
        }
    }
    __syncthreads();

    // ---- Pairwise quantile-Huber: item = (u, j-pair) ----
    const int nitems = nu * 25;
    for (int it = tid; it < nitems; it += NTHR) {
        const int u  = it / 25;
        const int jp = it - u * 25;

        const float2 v2 = *(const float2*)&value[(lo + u) * BQ + b * QQ + 2 * jp];
        unsigned long long nv2a, nv2b;
        {
            float na = -v2.x, nb = -v2.y;
            asm("mov.b64 %0, {%1, %1};" : "=l"(nv2a) : "f"(na));
            asm("mov.b64 %0, {%1, %1};" : "=l"(nv2b) : "f"(nb));
        }
        const unsigned long long MH2 = 0xBF000000BF000000ULL;   // (-0.5,-0.5)
        unsigned long long S2a = 0, D2a = 0, S2b = 0, D2b = 0;

        const ulonglong2* rp2 = (const ulonglong2*)&s_ret[u][0];
        #pragma unroll
        for (int p = 0; p < 12; ++p) {               // 48 returns via LDS.128
            ulonglong2 rr = rp2[p];
            PAIR2(rr.x, nv2a, S2a, D2a);
            PAIR2(rr.x, nv2b, S2b, D2b);
            PAIR2(rr.y, nv2a, S2a, D2a);
            PAIR2(rr.y, nv2b, S2b, D2b);
        }
        {                                            // returns 48, 49
            unsigned long long rt_ = *(const unsigned long long*)&s_ret[u][48];
            PAIR2(rt_, nv2a, S2a, D2a);
            PAIR2(rt_, nv2b, S2b, D2b);
        }

        float sl, sh, dl, dh;
        asm("mov.b64 {%0, %1}, %2;" : "=f"(sl), "=f"(sh) : "l"(S2a));
        asm("mov.b64 {%0, %1}, %2;" : "=f"(dl), "=f"(dh) : "l"(D2a));
        const float taua = (2 * jp + 0.5f) * (1.0f / QQ);
        s_part[u][2 * jp]     = fmaf(taua - 0.5f, dl + dh, 0.5f * (sl + sh));

        asm("mov.b64 {%0, %1}, %2;" : "=f"(sl), "=f"(sh) : "l"(S2b));
        asm("mov.b64 {%0, %1}, %2;" : "=f"(dl), "=f"(dh) : "l"(D2b));
        const float taub = (2 * jp + 1.5f) * (1.0f / QQ);
        s_part[u][2 * jp + 1] = fmaf(taub - 0.5f, dl + dh, 0.5f * (sl + sh));
    }
    __syncthreads();

    // ---- Deterministic fixed-order j-reduction ----
    if (tid < nu) {
        float s = 0.0f;
        #pragma unroll
        for (int j = 0; j < QQ; ++j) s += s_part[tid][j];
        out[(lo + tid) * BB + b] = s * (1.0f / QQ);
    }
}

extern "C" void kernel_launch(void* const* d_in, const int* in_sizes, int n_in,
                              void* d_out, int out_size)
{
    const float* reward    = (const float*)d_in[0];
    const int*   step_type = (const int*)  d_in[1];
    const float* discount  = (const float*)d_in[2];
    const float* value     = (const float*)d_in[3];
    const float* tvalue    = (const float*)d_in[4];
    float*       out       = (float*)d_out;

    dim3 gs(BQ / 2 / 128, NCH);                      // (100, 8)
    k_scan<<<gs, 128>>>(reward, step_type, discount, tvalue, out);

    dim3 gf(BB, 4);                                  // 2048 blocks
    k_fused<<<gf, NTHR>>>(reward, step_type, discount, value, tvalue, out);
}